// round 13
// baseline (speedup 1.0000x reference)
#include <cuda_runtime.h>
#include <cuda_bf16.h>
#include <math.h>

#define D_MODEL 1024
#define N_HEAD  16
#define T_SEQ   2048
#define BATCH   2
#define MTOT    4096
#define KDIM    1024

typedef __nv_bfloat16 bf16;

__device__ bf16 g_qh [(size_t)MTOT * 3 * D_MODEL];
__device__ bf16 g_ql [(size_t)MTOT * 3 * D_MODEL];
__device__ bf16 g_xh [(size_t)MTOT * D_MODEL];
__device__ bf16 g_xl [(size_t)MTOT * D_MODEL];
__device__ bf16 g_wqh[(size_t)3 * D_MODEL * D_MODEL];
__device__ bf16 g_wql[(size_t)3 * D_MODEL * D_MODEL];
__device__ bf16 g_woh[(size_t)D_MODEL * D_MODEL];
__device__ bf16 g_wol[(size_t)D_MODEL * D_MODEL];
__device__ bf16 g_ah [(size_t)MTOT * D_MODEL];
__device__ bf16 g_al [(size_t)MTOT * D_MODEL];

__device__ __forceinline__ unsigned int bpack(float a, float b)
{
    __nv_bfloat162 p = __floats2bfloat162_rn(a, b);
    return *(unsigned int*)&p;
}

// one fused split pass over x (4M), qkv_w (3M), out_w (1M) fp32 elements
#define SPLIT_N4_X  (MTOT * D_MODEL / 4)
#define SPLIT_N4_WQ (3 * D_MODEL * D_MODEL / 4)
#define SPLIT_N4_WO (D_MODEL * D_MODEL / 4)
#define SPLIT_N4_ALL (SPLIT_N4_X + SPLIT_N4_WQ + SPLIT_N4_WO)

__global__ void split_all_kernel(const float* __restrict__ x,
                                 const float* __restrict__ wq,
                                 const float* __restrict__ wo,
                                 bf16* __restrict__ xh, bf16* __restrict__ xl,
                                 bf16* __restrict__ wqh, bf16* __restrict__ wql,
                                 bf16* __restrict__ woh, bf16* __restrict__ wol)
{
    int i = blockIdx.x * blockDim.x + threadIdx.x;
    if (i >= SPLIT_N4_ALL) return;
    const float* in;
    bf16* hi;
    bf16* lo;
    int idx = i;
    if (idx < SPLIT_N4_X) {
        in = x; hi = xh; lo = xl;
    } else if (idx < SPLIT_N4_X + SPLIT_N4_WQ) {
        idx -= SPLIT_N4_X;
        in = wq; hi = wqh; lo = wql;
    } else {
        idx -= SPLIT_N4_X + SPLIT_N4_WQ;
        in = wo; hi = woh; lo = wol;
    }
    float4 v = ((const float4*)in)[idx];
    float hx = __bfloat162float(__float2bfloat16(v.x));
    float hy = __bfloat162float(__float2bfloat16(v.y));
    float hz = __bfloat162float(__float2bfloat16(v.z));
    float hw = __bfloat162float(__float2bfloat16(v.w));
    ((__nv_bfloat162*)hi)[2 * idx]     = __floats2bfloat162_rn(hx, hy);
    ((__nv_bfloat162*)hi)[2 * idx + 1] = __floats2bfloat162_rn(hz, hw);
    ((__nv_bfloat162*)lo)[2 * idx]     = __floats2bfloat162_rn(v.x - hx, v.y - hy);
    ((__nv_bfloat162*)lo)[2 * idx + 1] = __floats2bfloat162_rn(v.z - hz, v.w - hw);
}

__device__ __forceinline__ void cp16(unsigned int s, const void* g)
{
    asm volatile("cp.async.cg.shared.global [%0], [%1], 16;" :: "r"(s), "l"(g));
}
__device__ __forceinline__ void ldsm4(unsigned int* r, unsigned int a)
{
    asm volatile("ldmatrix.sync.aligned.m8n8.x4.shared.b16 {%0,%1,%2,%3}, [%4];"
                 : "=r"(r[0]), "=r"(r[1]), "=r"(r[2]), "=r"(r[3]) : "r"(a));
}
__device__ __forceinline__ void ldsm4t(unsigned int* r, unsigned int a)
{
    asm volatile("ldmatrix.sync.aligned.m8n8.x4.trans.shared.b16 {%0,%1,%2,%3}, [%4];"
                 : "=r"(r[0]), "=r"(r[1]), "=r"(r[2]), "=r"(r[3]) : "r"(a));
}
__device__ __forceinline__ void mma16816(float* c,
                                         const unsigned int* a,
                                         unsigned int e0, unsigned int e1)
{
    asm volatile(
        "mma.sync.aligned.m16n8k16.row.col.f32.bf16.bf16.f32 "
        "{%0,%1,%2,%3},{%4,%5,%6,%7},{%8,%9},{%0,%1,%2,%3};"
        : "+f"(c[0]), "+f"(c[1]), "+f"(c[2]), "+f"(c[3])
        : "r"(a[0]), "r"(a[1]), "r"(a[2]), "r"(a[3]), "r"(e0), "r"(e1));
}

// ---------------------------------------------------------------------------
// Fused 3-term bf16 GEMM. Round-7 inner loop, but 2-stage k32 ring with the
// attention kernel's proven pipeline ordering (wait 1 / sync / compute / sync
// / issue next-next). Halves barrier+wait events per K.
// ---------------------------------------------------------------------------
#define GP         24
#define GT_BYTES   (128 * GP * 2)        // 6144 per 128x16 tile
#define GSTG_BYTES (8 * GT_BYTES)        // 49152 per k32 stage (Ah,Al,Bh,Bl x2)
#define GSMEM      (2 * GSTG_BYTES)      // 98304 -> occ 2

template<int SPLIT>
__global__ __launch_bounds__(256, 2) void gemm_fused(
    const bf16* __restrict__ Ah, const bf16* __restrict__ Al,
    const bf16* __restrict__ Bh, const bf16* __restrict__ Bl,
    const float* __restrict__ bias, float* __restrict__ C,
    bf16* __restrict__ Ch, bf16* __restrict__ Cl, int N)
{
    extern __shared__ bf16 gsm[];
    const unsigned int SBM = (unsigned int)__cvta_generic_to_shared(gsm);

    const int t    = threadIdx.x;
    const int lane = t & 31;
    const int warp = t >> 5;
    const int wm   = warp & 1;
    const int wn   = warp >> 1;
    const int m0   = blockIdx.y * 128;
    const int n0   = blockIdx.x * 128;
    const int ldrow = t >> 1;
    const int ldoff = (t & 1) * 8;

    const unsigned int st_b = (unsigned int)(ldrow * GP + ldoff) * 2u;
    const unsigned int a_fb = (unsigned int)((wm * 64 + (lane & 15)) * GP + (lane >> 4) * 8) * 2u;
    const unsigned int b_fb = (unsigned int)((wn * 32 + (lane & 15)) * GP + (lane >> 4) * 8) * 2u;

    const size_t arow = (size_t)(m0 + ldrow) * KDIM + ldoff;
    const size_t brow = (size_t)(n0 + ldrow) * KDIM + ldoff;

    float acc[4][4][4];
#pragma unroll
    for (int i = 0; i < 4; i++)
#pragma unroll
        for (int j = 0; j < 4; j++)
#pragma unroll
            for (int r = 0; r < 4; r++) acc[i][j][r] = 0.f;

    // prologue: stage windows 0 and 1 (k = 0..31 and 32..63)
#pragma unroll
    for (int s = 0; s < 2; s++) {
        unsigned int db = SBM + (unsigned int)(s * GSTG_BYTES) + st_b;
#pragma unroll
        for (int half = 0; half < 2; half++) {
            int kk = s * 32 + half * 16;
            unsigned int hb = db + (unsigned int)(half * 4 * GT_BYTES);
            cp16(hb,                Ah + arow + kk);
            cp16(hb + GT_BYTES,     Al + arow + kk);
            cp16(hb + 2 * GT_BYTES, Bh + brow + kk);
            cp16(hb + 3 * GT_BYTES, Bl + brow + kk);
        }
        asm volatile("cp.async.commit_group;");
    }

    for (int j = 0; j < 32; j++) {        // window j covers k = 32j..32j+31
        if (j < 31) asm volatile("cp.async.wait_group 1;");
        else        asm volatile("cp.async.wait_group 0;");
        __syncthreads();

        const unsigned int wb = SBM + (unsigned int)((j & 1) * GSTG_BYTES);
#pragma unroll
        for (int ks = 0; ks < 2; ks++) {
            const unsigned int sb = wb + (unsigned int)(ks * 4 * GT_BYTES);
            unsigned int fah[4][4];
            unsigned int fal[4][4];
            unsigned int fbh[2][4];
            unsigned int fbl[2][4];
#pragma unroll
            for (int mf = 0; mf < 4; mf++) {
                ldsm4(fah[mf], sb + a_fb + (unsigned int)(mf * 16 * GP * 2));
                ldsm4(fal[mf], sb + GT_BYTES + a_fb + (unsigned int)(mf * 16 * GP * 2));
            }
#pragma unroll
            for (int pf = 0; pf < 2; pf++) {
                ldsm4(fbh[pf], sb + 2 * GT_BYTES + b_fb + (unsigned int)(pf * 16 * GP * 2));
                ldsm4(fbl[pf], sb + 3 * GT_BYTES + b_fb + (unsigned int)(pf * 16 * GP * 2));
            }

#pragma unroll
            for (int mf = 0; mf < 4; mf++)
#pragma unroll
                for (int pf = 0; pf < 2; pf++) {
                    mma16816(acc[mf][2 * pf],     fah[mf], fbh[pf][0], fbh[pf][2]);
                    mma16816(acc[mf][2 * pf + 1], fah[mf], fbh[pf][1], fbh[pf][3]);
                }
#pragma unroll
            for (int mf = 0; mf < 4; mf++)
#pragma unroll
                for (int pf = 0; pf < 2; pf++) {
                    mma16816(acc[mf][2 * pf],     fah[mf], fbl[pf][0], fbl[pf][2]);
                    mma16816(acc[mf][2 * pf + 1], fah[mf], fbl[pf][1], fbl[pf][3]);
                }
#pragma unroll
            for (int mf = 0; mf < 4; mf++)
#pragma unroll
                for (int pf = 0; pf < 2; pf++) {
                    mma16816(acc[mf][2 * pf],     fal[mf], fbh[pf][0], fbh[pf][2]);
                    mma16816(acc[mf][2 * pf + 1], fal[mf], fbh[pf][1], fbh[pf][3]);
                }
        }
        __syncthreads();

        if (j + 2 < 32) {
            unsigned int db = SBM + (unsigned int)((j & 1) * GSTG_BYTES) + st_b;
#pragma unroll
            for (int half = 0; half < 2; half++) {
                int kk = (j + 2) * 32 + half * 16;
                unsigned int hb = db + (unsigned int)(half * 4 * GT_BYTES);
                cp16(hb,                Ah + arow + kk);
                cp16(hb + GT_BYTES,     Al + arow + kk);
                cp16(hb + 2 * GT_BYTES, Bh + brow + kk);
                cp16(hb + 3 * GT_BYTES, Bl + brow + kk);
            }
            asm volatile("cp.async.commit_group;");
        }
    }

    const int gr = lane >> 2;
    const int gc = (lane & 3) * 2;
#pragma unroll
    for (int mf = 0; mf < 4; mf++) {
#pragma unroll
        for (int nf = 0; nf < 4; nf++) {
            int m = m0 + wm * 64 + mf * 16 + gr;
            int n = n0 + wn * 32 + nf * 8 + gc;
            float b0 = bias[n];
            float b1 = bias[n + 1];
            float x0 = acc[mf][nf][0] + b0;
            float x1 = acc[mf][nf][1] + b1;
            float y0 = acc[mf][nf][2] + b0;
            float y1 = acc[mf][nf][3] + b1;
            if (SPLIT) {
                float hx0 = __bfloat162float(__float2bfloat16(x0));
                float hx1 = __bfloat162float(__float2bfloat16(x1));
                float hy0 = __bfloat162float(__float2bfloat16(y0));
                float hy1 = __bfloat162float(__float2bfloat16(y1));
                *(__nv_bfloat162*)&Ch[(size_t)m * N + n] =
                    __floats2bfloat162_rn(hx0, hx1);
                *(__nv_bfloat162*)&Cl[(size_t)m * N + n] =
                    __floats2bfloat162_rn(x0 - hx0, x1 - hx1);
                *(__nv_bfloat162*)&Ch[(size_t)(m + 8) * N + n] =
                    __floats2bfloat162_rn(hy0, hy1);
                *(__nv_bfloat162*)&Cl[(size_t)(m + 8) * N + n] =
                    __floats2bfloat162_rn(y0 - hy0, y1 - hy1);
            } else {
                float2 v0;
                v0.x = x0; v0.y = x1;
                float2 v1;
                v1.x = y0; v1.y = y1;
                *(float2*)&C[(size_t)m * N + n]       = v0;
                *(float2*)&C[(size_t)(m + 8) * N + n] = v1;
            }
        }
    }
}

// ---------------------------------------------------------------------------
// Tensor-core flash attention (round-11: S-tile 64, 2 CTAs/SM) — unchanged.
// ---------------------------------------------------------------------------
#define AP         72
#define AT_BYTES   (64 * AP * 2)
#define ASTG_BYTES (4 * AT_BYTES)
#define ASMEM      (2 * ASTG_BYTES)

__device__ __forceinline__ void attn_issue_tile(unsigned int SBM, int stage,
                                                int tile, int b, int h, int t)
{
    const int rowstr = 3 * D_MODEL;
#pragma unroll
    for (int i = 0; i < 2; i++) {
        int slot = i * 256 + t;
        int r  = slot >> 3;
        int cc = (slot & 7) * 8;
        unsigned int d = SBM + (unsigned int)(stage * ASTG_BYTES)
                       + (unsigned int)((r * AP + cc) * 2);
        size_t base = (size_t)(b * T_SEQ + tile * 64 + r) * rowstr + h * 64 + cc;
        cp16(d,                g_qh + base + D_MODEL);
        cp16(d + AT_BYTES,     g_ql + base + D_MODEL);
        cp16(d + 2 * AT_BYTES, g_qh + base + 2 * D_MODEL);
        cp16(d + 3 * AT_BYTES, g_ql + base + 2 * D_MODEL);
    }
    asm volatile("cp.async.commit_group;");
}

__global__ __launch_bounds__(256, 2) void attn_tc_kernel()
{
    extern __shared__ bf16 smb[];
    const unsigned int SBM = (unsigned int)__cvta_generic_to_shared(smb);

    const int t    = threadIdx.x;
    const int lane = t & 31;
    const int w    = t >> 5;
    const int b    = blockIdx.z;
    const int h    = blockIdx.y;
    const int q0   = blockIdx.x * 128;
    const int rowstr = 3 * D_MODEL;
    const int gr   = lane >> 2;
    const int gc   = lane & 3;

#pragma unroll
    for (int i = 0; i < 4; i++) {
        int slot = i * 256 + t;
        int r  = slot >> 3;
        int cc = (slot & 7) * 8;
        unsigned int d = SBM + (unsigned int)((r * AP + cc) * 2);
        size_t base = (size_t)(b * T_SEQ + q0 + r) * rowstr + h * 64 + cc;
        cp16(d,                g_qh + base);
        cp16(d + 128 * AP * 2, g_ql + base);
    }
    asm volatile("cp.async.commit_group;");
    asm volatile("cp.async.wait_group 0;");
    __syncthreads();

    unsigned int qfh[4][4];
    unsigned int qfl[4][4];
    {
        const unsigned int qoff =
            (unsigned int)((w * 16 + (lane & 15)) * AP + (lane >> 4) * 8) * 2u;
#pragma unroll
        for (int kc = 0; kc < 4; kc++) {
            ldsm4(qfh[kc], SBM + qoff + (unsigned int)(kc * 32));
            ldsm4(qfl[kc], SBM + (unsigned int)(128 * AP * 2) + qoff + (unsigned int)(kc * 32));
        }
    }
    __syncthreads();

    attn_issue_tile(SBM, 0, 0, b, h, t);
    attn_issue_tile(SBM, 1, 1, b, h, t);

    float sc[8][4];
    float o[8][4];
#pragma unroll
    for (int nf = 0; nf < 8; nf++)
#pragma unroll
        for (int r = 0; r < 4; r++) o[nf][r] = 0.f;
    float rm0 = -1e30f, rm1 = -1e30f, rl0 = 0.f, rl1 = 0.f;

    const unsigned int kfoff =
        (unsigned int)((lane & 15) * AP + (lane >> 4) * 8) * 2u;

    for (int it = 0; it < 32; it++) {
        if (it < 31) asm volatile("cp.async.wait_group 1;");
        else         asm volatile("cp.async.wait_group 0;");
        __syncthreads();

        const unsigned int sb = SBM + (unsigned int)((it & 1) * ASTG_BYTES);

#pragma unroll
        for (int nf = 0; nf < 8; nf++)
#pragma unroll
            for (int r = 0; r < 4; r++) sc[nf][r] = 0.f;

#pragma unroll
        for (int kc = 0; kc < 4; kc++) {
            unsigned int kbh[4][4];
            unsigned int kbl[4][4];
#pragma unroll
            for (int j = 0; j < 4; j++) {
                const unsigned int roff =
                    (unsigned int)(j * 16 * AP * 2) + (unsigned int)(kc * 32);
                ldsm4(kbh[j], sb + kfoff + roff);
                ldsm4(kbl[j], sb + AT_BYTES + kfoff + roff);
            }
#pragma unroll
            for (int j = 0; j < 4; j++) {
                mma16816(sc[2 * j],     qfh[kc], kbh[j][0], kbh[j][2]);
                mma16816(sc[2 * j + 1], qfh[kc], kbh[j][1], kbh[j][3]);
            }
#pragma unroll
            for (int j = 0; j < 4; j++) {
                mma16816(sc[2 * j],     qfh[kc], kbl[j][0], kbl[j][2]);
                mma16816(sc[2 * j + 1], qfh[kc], kbl[j][1], kbl[j][3]);
            }
#pragma unroll
            for (int j = 0; j < 4; j++) {
                mma16816(sc[2 * j],     qfl[kc], kbh[j][0], kbh[j][2]);
                mma16816(sc[2 * j + 1], qfl[kc], kbh[j][1], kbh[j][3]);
            }
        }

#pragma unroll
        for (int nf = 0; nf < 8; nf++) {
            sc[nf][0] *= 0.125f;
            sc[nf][1] *= 0.125f;
            sc[nf][2] *= 0.125f;
            sc[nf][3] *= 0.125f;
        }
        float mx0 = -1e30f, mx1 = -1e30f;
#pragma unroll
        for (int nf = 0; nf < 8; nf++) {
            mx0 = fmaxf(mx0, fmaxf(sc[nf][0], sc[nf][1]));
            mx1 = fmaxf(mx1, fmaxf(sc[nf][2], sc[nf][3]));
        }
        mx0 = fmaxf(mx0, __shfl_xor_sync(0xffffffffu, mx0, 1));
        mx0 = fmaxf(mx0, __shfl_xor_sync(0xffffffffu, mx0, 2));
        mx1 = fmaxf(mx1, __shfl_xor_sync(0xffffffffu, mx1, 1));
        mx1 = fmaxf(mx1, __shfl_xor_sync(0xffffffffu, mx1, 2));
        float mn0 = fmaxf(rm0, mx0);
        float mn1 = fmaxf(rm1, mx1);
        float c0 = __expf(rm0 - mn0);
        float c1 = __expf(rm1 - mn1);
        rm0 = mn0;
        rm1 = mn1;
        float ls0 = 0.f, ls1 = 0.f;
#pragma unroll
        for (int nf = 0; nf < 8; nf++) {
            sc[nf][0] = __expf(sc[nf][0] - mn0);
            sc[nf][1] = __expf(sc[nf][1] - mn0);
            sc[nf][2] = __expf(sc[nf][2] - mn1);
            sc[nf][3] = __expf(sc[nf][3] - mn1);
            ls0 += sc[nf][0] + sc[nf][1];
            ls1 += sc[nf][2] + sc[nf][3];
        }
        ls0 += __shfl_xor_sync(0xffffffffu, ls0, 1);
        ls0 += __shfl_xor_sync(0xffffffffu, ls0, 2);
        ls1 += __shfl_xor_sync(0xffffffffu, ls1, 1);
        ls1 += __shfl_xor_sync(0xffffffffu, ls1, 2);
        rl0 = rl0 * c0 + ls0;
        rl1 = rl1 * c1 + ls1;
#pragma unroll
        for (int nf = 0; nf < 8; nf++) {
            o[nf][0] *= c0;
            o[nf][1] *= c0;
            o[nf][2] *= c1;
            o[nf][3] *= c1;
        }

#pragma unroll
        for (int kc = 0; kc < 4; kc++) {
            float v00 = sc[2 * kc][0],     v01 = sc[2 * kc][1];
            float v10 = sc[2 * kc][2],     v11 = sc[2 * kc][3];
            float v20 = sc[2 * kc + 1][0], v21 = sc[2 * kc + 1][1];
            float v30 = sc[2 * kc + 1][2], v31 = sc[2 * kc + 1][3];
            float h00 = __bfloat162float(__float2bfloat16(v00));
            float h01 = __bfloat162float(__float2bfloat16(v01));
            float h10 = __bfloat162float(__float2bfloat16(v10));
            float h11 = __bfloat162float(__float2bfloat16(v11));
            float h20 = __bfloat162float(__float2bfloat16(v20));
            float h21 = __bfloat162float(__float2bfloat16(v21));
            float h30 = __bfloat162float(__float2bfloat16(v30));
            float h31 = __bfloat162float(__float2bfloat16(v31));
            unsigned int pa_h[4];
            unsigned int pa_l[4];
            pa_h[0] = bpack(h00, h01);
            pa_h[1] = bpack(h10, h11);
            pa_h[2] = bpack(h20, h21);
            pa_h[3] = bpack(h30, h31);
            pa_l[0] = bpack(v00 - h00, v01 - h01);
            pa_l[1] = bpack(v10 - h10, v11 - h11);
            pa_l[2] = bpack(v20 - h20, v21 - h21);
            pa_l[3] = bpack(v30 - h30, v31 - h31);

            const unsigned int soff = (unsigned int)(kc * 16 * AP * 2);
            unsigned int vbh[4][4];
            unsigned int vbl[4][4];
#pragma unroll
            for (int dg = 0; dg < 4; dg++) {
                ldsm4t(vbh[dg], sb + 2 * AT_BYTES + kfoff + soff + (unsigned int)(dg * 32));
                ldsm4t(vbl[dg], sb + 3 * AT_BYTES + kfoff + soff + (unsigned int)(dg * 32));
            }
#pragma unroll
            for (int dg = 0; dg < 4; dg++) {
                mma16816(o[2 * dg],     pa_h, vbh[dg][0], vbh[dg][1]);
                mma16816(o[2 * dg + 1], pa_h, vbh[dg][2], vbh[dg][3]);
            }
#pragma unroll
            for (int dg = 0; dg < 4; dg++) {
                mma16816(o[2 * dg],     pa_h, vbl[dg][0], vbl[dg][1]);
                mma16816(o[2 * dg + 1], pa_h, vbl[dg][2], vbl[dg][3]);
            }
#pragma unroll
            for (int dg = 0; dg < 4; dg++) {
                mma16816(o[2 * dg],     pa_l, vbh[dg][0], vbh[dg][1]);
                mma16816(o[2 * dg + 1], pa_l, vbh[dg][2], vbh[dg][3]);
            }
        }
        __syncthreads();

        if (it + 2 < 32)
            attn_issue_tile(SBM, it & 1, it + 2, b, h, t);
    }

    float inv0 = 1.f / rl0;
    float inv1 = 1.f / rl1;
    const int row0 = q0 + w * 16 + gr;
    const int row1 = row0 + 8;
#pragma unroll
    for (int nf = 0; nf < 8; nf++) {
        int d = nf * 8 + 2 * gc;
        float a0 = o[nf][0] * inv0;
        float a1 = o[nf][1] * inv0;
        float b0v = o[nf][2] * inv1;
        float b1v = o[nf][3] * inv1;
        size_t off0 = (size_t)(b * T_SEQ + row0) * D_MODEL + h * 64 + d;
        size_t off1 = (size_t)(b * T_SEQ + row1) * D_MODEL + h * 64 + d;
        float ha0 = __bfloat162float(__float2bfloat16(a0));
        float ha1 = __bfloat162float(__float2bfloat16(a1));
        float hb0 = __bfloat162float(__float2bfloat16(b0v));
        float hb1 = __bfloat162float(__float2bfloat16(b1v));
        *(__nv_bfloat162*)&g_ah[off0] = __floats2bfloat162_rn(ha0, ha1);
        *(__nv_bfloat162*)&g_al[off0] = __floats2bfloat162_rn(a0 - ha0, a1 - ha1);
        *(__nv_bfloat162*)&g_ah[off1] = __floats2bfloat162_rn(hb0, hb1);
        *(__nv_bfloat162*)&g_al[off1] = __floats2bfloat162_rn(b0v - hb0, b1v - hb1);
    }
}

// ---------------------------------------------------------------------------
extern "C" void kernel_launch(void* const* d_in, const int* in_sizes, int n_in,
                              void* d_out, int out_size)
{
    const float* x      = (const float*)d_in[0];
    const float* qkv_w  = (const float*)d_in[1];
    const float* qkv_b  = (const float*)d_in[2];
    const float* out_w  = (const float*)d_in[3];
    const float* out_b  = (const float*)d_in[4];
    float* out = (float*)d_out;

    bf16* xh;  bf16* xl;
    bf16* wqh; bf16* wql;
    bf16* woh; bf16* wol;
    bf16* qh;  bf16* ql;
    bf16* ah;  bf16* al;
    cudaGetSymbolAddress((void**)&xh,  g_xh);
    cudaGetSymbolAddress((void**)&xl,  g_xl);
    cudaGetSymbolAddress((void**)&wqh, g_wqh);
    cudaGetSymbolAddress((void**)&wql, g_wql);
    cudaGetSymbolAddress((void**)&woh, g_woh);
    cudaGetSymbolAddress((void**)&wol, g_wol);
    cudaGetSymbolAddress((void**)&qh,  g_qh);
    cudaGetSymbolAddress((void**)&ql,  g_ql);
    cudaGetSymbolAddress((void**)&ah,  g_ah);
    cudaGetSymbolAddress((void**)&al,  g_al);

    cudaFuncSetAttribute(gemm_fused<1>,
                         cudaFuncAttributeMaxDynamicSharedMemorySize, GSMEM);
    cudaFuncSetAttribute(gemm_fused<0>,
                         cudaFuncAttributeMaxDynamicSharedMemorySize, GSMEM);
    cudaFuncSetAttribute(attn_tc_kernel,
                         cudaFuncAttributeMaxDynamicSharedMemorySize, ASMEM);

    split_all_kernel<<<(SPLIT_N4_ALL + 255) / 256, 256>>>(
        x, qkv_w, out_w, xh, xl, wqh, wql, woh, wol);

    {
        dim3 grid(3 * D_MODEL / 128, MTOT / 128);
        gemm_fused<1><<<grid, 256, GSMEM>>>(xh, xl, wqh, wql, qkv_b,
                                            (float*)0, qh, ql, 3 * D_MODEL);
    }
    {
        dim3 grid(T_SEQ / 128, N_HEAD, BATCH);
        attn_tc_kernel<<<grid, 256, ASMEM>>>();
    }
    {
        dim3 grid(D_MODEL / 128, MTOT / 128);
        gemm_fused<0><<<grid, 256, GSMEM>>>(ah, al, woh, wol, out_b,
                                            out, (bf16*)0, (bf16*)0, D_MODEL);
    }
}

// round 14
// speedup vs baseline: 1.0486x; 1.0486x over previous
#include <cuda_runtime.h>
#include <cuda_bf16.h>
#include <math.h>

#define D_MODEL 1024
#define N_HEAD  16
#define T_SEQ   2048
#define BATCH   2
#define MTOT    4096
#define KDIM    1024

typedef __nv_bfloat16 bf16;

__device__ bf16 g_qh [(size_t)MTOT * 3 * D_MODEL];
__device__ bf16 g_ql [(size_t)MTOT * 3 * D_MODEL];
__device__ bf16 g_xh [(size_t)MTOT * D_MODEL];
__device__ bf16 g_xl [(size_t)MTOT * D_MODEL];
__device__ bf16 g_wqh[(size_t)3 * D_MODEL * D_MODEL];
__device__ bf16 g_wql[(size_t)3 * D_MODEL * D_MODEL];
__device__ bf16 g_woh[(size_t)D_MODEL * D_MODEL];
__device__ bf16 g_wol[(size_t)D_MODEL * D_MODEL];
__device__ bf16 g_ah [(size_t)MTOT * D_MODEL];
__device__ bf16 g_al [(size_t)MTOT * D_MODEL];

__device__ __forceinline__ unsigned int bpack(float a, float b)
{
    __nv_bfloat162 p = __floats2bfloat162_rn(a, b);
    return *(unsigned int*)&p;
}

// one fused split pass over x (4M), qkv_w (3M), out_w (1M) fp32 elements
#define SPLIT_N4_X  (MTOT * D_MODEL / 4)
#define SPLIT_N4_WQ (3 * D_MODEL * D_MODEL / 4)
#define SPLIT_N4_WO (D_MODEL * D_MODEL / 4)
#define SPLIT_N4_ALL (SPLIT_N4_X + SPLIT_N4_WQ + SPLIT_N4_WO)

__global__ void split_all_kernel(const float* __restrict__ x,
                                 const float* __restrict__ wq,
                                 const float* __restrict__ wo,
                                 bf16* __restrict__ xh, bf16* __restrict__ xl,
                                 bf16* __restrict__ wqh, bf16* __restrict__ wql,
                                 bf16* __restrict__ woh, bf16* __restrict__ wol)
{
    int i = blockIdx.x * blockDim.x + threadIdx.x;
    if (i >= SPLIT_N4_ALL) return;
    const float* in;
    bf16* hi;
    bf16* lo;
    int idx = i;
    if (idx < SPLIT_N4_X) {
        in = x; hi = xh; lo = xl;
    } else if (idx < SPLIT_N4_X + SPLIT_N4_WQ) {
        idx -= SPLIT_N4_X;
        in = wq; hi = wqh; lo = wql;
    } else {
        idx -= SPLIT_N4_X + SPLIT_N4_WQ;
        in = wo; hi = woh; lo = wol;
    }
    float4 v = ((const float4*)in)[idx];
    float hx = __bfloat162float(__float2bfloat16(v.x));
    float hy = __bfloat162float(__float2bfloat16(v.y));
    float hz = __bfloat162float(__float2bfloat16(v.z));
    float hw = __bfloat162float(__float2bfloat16(v.w));
    ((__nv_bfloat162*)hi)[2 * idx]     = __floats2bfloat162_rn(hx, hy);
    ((__nv_bfloat162*)hi)[2 * idx + 1] = __floats2bfloat162_rn(hz, hw);
    ((__nv_bfloat162*)lo)[2 * idx]     = __floats2bfloat162_rn(v.x - hx, v.y - hy);
    ((__nv_bfloat162*)lo)[2 * idx + 1] = __floats2bfloat162_rn(v.z - hz, v.w - hw);
}

__device__ __forceinline__ void cp16(unsigned int s, const void* g)
{
    asm volatile("cp.async.cg.shared.global [%0], [%1], 16;" :: "r"(s), "l"(g));
}
__device__ __forceinline__ void ldsm4(unsigned int* r, unsigned int a)
{
    asm volatile("ldmatrix.sync.aligned.m8n8.x4.shared.b16 {%0,%1,%2,%3}, [%4];"
                 : "=r"(r[0]), "=r"(r[1]), "=r"(r[2]), "=r"(r[3]) : "r"(a));
}
__device__ __forceinline__ void ldsm4t(unsigned int* r, unsigned int a)
{
    asm volatile("ldmatrix.sync.aligned.m8n8.x4.trans.shared.b16 {%0,%1,%2,%3}, [%4];"
                 : "=r"(r[0]), "=r"(r[1]), "=r"(r[2]), "=r"(r[3]) : "r"(a));
}
__device__ __forceinline__ void mma16816(float* c,
                                         const unsigned int* a,
                                         unsigned int e0, unsigned int e1)
{
    asm volatile(
        "mma.sync.aligned.m16n8k16.row.col.f32.bf16.bf16.f32 "
        "{%0,%1,%2,%3},{%4,%5,%6,%7},{%8,%9},{%0,%1,%2,%3};"
        : "+f"(c[0]), "+f"(c[1]), "+f"(c[2]), "+f"(c[3])
        : "r"(a[0]), "r"(a[1]), "r"(a[2]), "r"(a[3]), "r"(e0), "r"(e1));
}

// ---------------------------------------------------------------------------
// Fused 3-term bf16 GEMM — exact round-7 configuration (best measured):
// 3-stage k16 ring, wait_group 1, term-major MMA issue, 256 threads, occ 2.
// ---------------------------------------------------------------------------
#define GP         24
#define GT_BYTES   (128 * GP * 2)
#define GSTG_BYTES (4 * GT_BYTES)
#define GSMEM      (3 * GSTG_BYTES)

template<int SPLIT>
__global__ __launch_bounds__(256, 2) void gemm_fused(
    const bf16* __restrict__ Ah, const bf16* __restrict__ Al,
    const bf16* __restrict__ Bh, const bf16* __restrict__ Bl,
    const float* __restrict__ bias, float* __restrict__ C,
    bf16* __restrict__ Ch, bf16* __restrict__ Cl, int N)
{
    extern __shared__ bf16 gsm[];
    const unsigned int SBM = (unsigned int)__cvta_generic_to_shared(gsm);

    const int t    = threadIdx.x;
    const int lane = t & 31;
    const int warp = t >> 5;
    const int wm   = warp & 1;
    const int wn   = warp >> 1;
    const int m0   = blockIdx.y * 128;
    const int n0   = blockIdx.x * 128;
    const int ldrow = t >> 1;
    const int ldoff = (t & 1) * 8;

    const unsigned int st_b = (unsigned int)(ldrow * GP + ldoff) * 2u;
    const unsigned int a_fb = (unsigned int)((wm * 64 + (lane & 15)) * GP + (lane >> 4) * 8) * 2u;
    const unsigned int b_fb = (unsigned int)((wn * 32 + (lane & 15)) * GP + (lane >> 4) * 8) * 2u;

    const size_t arow = (size_t)(m0 + ldrow) * KDIM + ldoff;
    const size_t brow = (size_t)(n0 + ldrow) * KDIM + ldoff;

    float acc[4][4][4];
#pragma unroll
    for (int i = 0; i < 4; i++)
#pragma unroll
        for (int j = 0; j < 4; j++)
#pragma unroll
            for (int r = 0; r < 4; r++) acc[i][j][r] = 0.f;

#pragma unroll
    for (int s = 0; s < 2; s++) {
        unsigned int db = SBM + (unsigned int)(s * GSTG_BYTES) + st_b;
        int kk = s * 16;
        cp16(db,                Ah + arow + kk);
        cp16(db + GT_BYTES,     Al + arow + kk);
        cp16(db + 2 * GT_BYTES, Bh + brow + kk);
        cp16(db + 3 * GT_BYTES, Bl + brow + kk);
        asm volatile("cp.async.commit_group;");
    }

    int stg = 0;
    for (int s = 0; s < 64; s++) {
        if (s < 63) asm volatile("cp.async.wait_group 1;");
        else        asm volatile("cp.async.wait_group 0;");
        __syncthreads();

        const unsigned int sb = SBM + (unsigned int)(stg * GSTG_BYTES);
        unsigned int fah[4][4];
        unsigned int fal[4][4];
        unsigned int fbh[2][4];
        unsigned int fbl[2][4];
#pragma unroll
        for (int mf = 0; mf < 4; mf++) {
            ldsm4(fah[mf], sb + a_fb + (unsigned int)(mf * 16 * GP * 2));
            ldsm4(fal[mf], sb + GT_BYTES + a_fb + (unsigned int)(mf * 16 * GP * 2));
        }
#pragma unroll
        for (int pf = 0; pf < 2; pf++) {
            ldsm4(fbh[pf], sb + 2 * GT_BYTES + b_fb + (unsigned int)(pf * 16 * GP * 2));
            ldsm4(fbl[pf], sb + 3 * GT_BYTES + b_fb + (unsigned int)(pf * 16 * GP * 2));
        }

#pragma unroll
        for (int mf = 0; mf < 4; mf++)
#pragma unroll
            for (int pf = 0; pf < 2; pf++) {
                mma16816(acc[mf][2 * pf],     fah[mf], fbh[pf][0], fbh[pf][2]);
                mma16816(acc[mf][2 * pf + 1], fah[mf], fbh[pf][1], fbh[pf][3]);
            }
#pragma unroll
        for (int mf = 0; mf < 4; mf++)
#pragma unroll
            for (int pf = 0; pf < 2; pf++) {
                mma16816(acc[mf][2 * pf],     fah[mf], fbl[pf][0], fbl[pf][2]);
                mma16816(acc[mf][2 * pf + 1], fah[mf], fbl[pf][1], fbl[pf][3]);
            }
#pragma unroll
        for (int mf = 0; mf < 4; mf++)
#pragma unroll
            for (int pf = 0; pf < 2; pf++) {
                mma16816(acc[mf][2 * pf],     fal[mf], fbh[pf][0], fbh[pf][2]);
                mma16816(acc[mf][2 * pf + 1], fal[mf], fbh[pf][1], fbh[pf][3]);
            }

        if (s + 2 < 64) {
            int st2 = stg + 2;
            if (st2 >= 3) st2 -= 3;
            unsigned int db = SBM + (unsigned int)(st2 * GSTG_BYTES) + st_b;
            int kk = (s + 2) * 16;
            cp16(db,                Ah + arow + kk);
            cp16(db + GT_BYTES,     Al + arow + kk);
            cp16(db + 2 * GT_BYTES, Bh + brow + kk);
            cp16(db + 3 * GT_BYTES, Bl + brow + kk);
            asm volatile("cp.async.commit_group;");
        }
        stg++;
        if (stg == 3) stg = 0;
    }

    const int gr = lane >> 2;
    const int gc = (lane & 3) * 2;
#pragma unroll
    for (int mf = 0; mf < 4; mf++) {
#pragma unroll
        for (int nf = 0; nf < 4; nf++) {
            int m = m0 + wm * 64 + mf * 16 + gr;
            int n = n0 + wn * 32 + nf * 8 + gc;
            float b0 = bias[n];
            float b1 = bias[n + 1];
            float x0 = acc[mf][nf][0] + b0;
            float x1 = acc[mf][nf][1] + b1;
            float y0 = acc[mf][nf][2] + b0;
            float y1 = acc[mf][nf][3] + b1;
            if (SPLIT) {
                float hx0 = __bfloat162float(__float2bfloat16(x0));
                float hx1 = __bfloat162float(__float2bfloat16(x1));
                float hy0 = __bfloat162float(__float2bfloat16(y0));
                float hy1 = __bfloat162float(__float2bfloat16(y1));
                *(__nv_bfloat162*)&Ch[(size_t)m * N + n] =
                    __floats2bfloat162_rn(hx0, hx1);
                *(__nv_bfloat162*)&Cl[(size_t)m * N + n] =
                    __floats2bfloat162_rn(x0 - hx0, x1 - hx1);
                *(__nv_bfloat162*)&Ch[(size_t)(m + 8) * N + n] =
                    __floats2bfloat162_rn(hy0, hy1);
                *(__nv_bfloat162*)&Cl[(size_t)(m + 8) * N + n] =
                    __floats2bfloat162_rn(y0 - hy0, y1 - hy1);
            } else {
                float2 v0;
                v0.x = x0; v0.y = x1;
                float2 v1;
                v1.x = y0; v1.y = y1;
                *(float2*)&C[(size_t)m * N + n]       = v0;
                *(float2*)&C[(size_t)(m + 8) * N + n] = v1;
            }
        }
    }
}

// ---------------------------------------------------------------------------
// Tensor-core flash attention — exact round-7 configuration (best measured):
// S-tile 128, occ 1, 2-stage ring, grouped QK^T, hoisted PV loads.
// ---------------------------------------------------------------------------
#define AP         72
#define AT_BYTES   (128 * AP * 2)
#define ASTG_BYTES (4 * AT_BYTES)
#define ASMEM      (2 * ASTG_BYTES)

__device__ __forceinline__ void attn_issue_tile(unsigned int SBM, int stage,
                                                int tile, int b, int h, int t)
{
    const int rowstr = 3 * D_MODEL;
#pragma unroll
    for (int i = 0; i < 4; i++) {
        int slot = i * 256 + t;
        int r  = slot >> 3;
        int cc = (slot & 7) * 8;
        unsigned int d = SBM + (unsigned int)(stage * ASTG_BYTES)
                       + (unsigned int)((r * AP + cc) * 2);
        size_t base = (size_t)(b * T_SEQ + tile * 128 + r) * rowstr + h * 64 + cc;
        cp16(d,                g_qh + base + D_MODEL);
        cp16(d + AT_BYTES,     g_ql + base + D_MODEL);
        cp16(d + 2 * AT_BYTES, g_qh + base + 2 * D_MODEL);
        cp16(d + 3 * AT_BYTES, g_ql + base + 2 * D_MODEL);
    }
    asm volatile("cp.async.commit_group;");
}

__global__ __launch_bounds__(256, 1) void attn_tc_kernel()
{
    extern __shared__ bf16 smb[];
    const unsigned int SBM = (unsigned int)__cvta_generic_to_shared(smb);

    const int t    = threadIdx.x;
    const int lane = t & 31;
    const int w    = t >> 5;
    const int b    = blockIdx.z;
    const int h    = blockIdx.y;
    const int q0   = blockIdx.x * 128;
    const int rowstr = 3 * D_MODEL;
    const int gr   = lane >> 2;
    const int gc   = lane & 3;

#pragma unroll
    for (int i = 0; i < 4; i++) {
        int slot = i * 256 + t;
        int r  = slot >> 3;
        int cc = (slot & 7) * 8;
        unsigned int d = SBM + (unsigned int)((r * AP + cc) * 2);
        size_t base = (size_t)(b * T_SEQ + q0 + r) * rowstr + h * 64 + cc;
        cp16(d,            g_qh + base);
        cp16(d + AT_BYTES, g_ql + base);
    }
    asm volatile("cp.async.commit_group;");
    asm volatile("cp.async.wait_group 0;");
    __syncthreads();

    unsigned int qfh[4][4];
    unsigned int qfl[4][4];
    {
        const unsigned int qoff =
            (unsigned int)((w * 16 + (lane & 15)) * AP + (lane >> 4) * 8) * 2u;
#pragma unroll
        for (int kc = 0; kc < 4; kc++) {
            ldsm4(qfh[kc], SBM + qoff + (unsigned int)(kc * 32));
            ldsm4(qfl[kc], SBM + AT_BYTES + qoff + (unsigned int)(kc * 32));
        }
    }
    __syncthreads();

    attn_issue_tile(SBM, 0, 0, b, h, t);
    attn_issue_tile(SBM, 1, 1, b, h, t);

    float sc[16][4];
    float o[8][4];
#pragma unroll
    for (int nf = 0; nf < 8; nf++)
#pragma unroll
        for (int r = 0; r < 4; r++) o[nf][r] = 0.f;
    float rm0 = -1e30f, rm1 = -1e30f, rl0 = 0.f, rl1 = 0.f;

    const unsigned int kfoff =
        (unsigned int)((lane & 15) * AP + (lane >> 4) * 8) * 2u;

    for (int it = 0; it < 16; it++) {
        if (it < 15) asm volatile("cp.async.wait_group 1;");
        else         asm volatile("cp.async.wait_group 0;");
        __syncthreads();

        const unsigned int sb = SBM + (unsigned int)((it & 1) * ASTG_BYTES);

#pragma unroll
        for (int nf = 0; nf < 16; nf++)
#pragma unroll
            for (int r = 0; r < 4; r++) sc[nf][r] = 0.f;

#pragma unroll
        for (int g = 0; g < 2; g++) {
#pragma unroll
            for (int kc = 0; kc < 4; kc++) {
                unsigned int kbh[4][4];
                unsigned int kbl[4][4];
#pragma unroll
                for (int j = 0; j < 4; j++) {
                    const unsigned int roff =
                        (unsigned int)((g * 4 + j) * 16 * AP * 2) +
                        (unsigned int)(kc * 32);
                    ldsm4(kbh[j], sb + kfoff + roff);
                    ldsm4(kbl[j], sb + AT_BYTES + kfoff + roff);
                }
#pragma unroll
                for (int j = 0; j < 4; j++) {
                    int a0 = 2 * (g * 4 + j);
                    mma16816(sc[a0],     qfh[kc], kbh[j][0], kbh[j][2]);
                    mma16816(sc[a0 + 1], qfh[kc], kbh[j][1], kbh[j][3]);
                }
#pragma unroll
                for (int j = 0; j < 4; j++) {
                    int a0 = 2 * (g * 4 + j);
                    mma16816(sc[a0],     qfh[kc], kbl[j][0], kbl[j][2]);
                    mma16816(sc[a0 + 1], qfh[kc], kbl[j][1], kbl[j][3]);
                }
#pragma unroll
                for (int j = 0; j < 4; j++) {
                    int a0 = 2 * (g * 4 + j);
                    mma16816(sc[a0],     qfl[kc], kbh[j][0], kbh[j][2]);
                    mma16816(sc[a0 + 1], qfl[kc], kbh[j][1], kbh[j][3]);
                }
            }
        }

#pragma unroll
        for (int nf = 0; nf < 16; nf++) {
            sc[nf][0] *= 0.125f;
            sc[nf][1] *= 0.125f;
            sc[nf][2] *= 0.125f;
            sc[nf][3] *= 0.125f;
        }
        float mx0 = -1e30f, mx1 = -1e30f;
#pragma unroll
        for (int nf = 0; nf < 16; nf++) {
            mx0 = fmaxf(mx0, fmaxf(sc[nf][0], sc[nf][1]));
            mx1 = fmaxf(mx1, fmaxf(sc[nf][2], sc[nf][3]));
        }
        mx0 = fmaxf(mx0, __shfl_xor_sync(0xffffffffu, mx0, 1));
        mx0 = fmaxf(mx0, __shfl_xor_sync(0xffffffffu, mx0, 2));
        mx1 = fmaxf(mx1, __shfl_xor_sync(0xffffffffu, mx1, 1));
        mx1 = fmaxf(mx1, __shfl_xor_sync(0xffffffffu, mx1, 2));
        float mn0 = fmaxf(rm0, mx0);
        float mn1 = fmaxf(rm1, mx1);
        float c0 = __expf(rm0 - mn0);
        float c1 = __expf(rm1 - mn1);
        rm0 = mn0;
        rm1 = mn1;
        float ls0 = 0.f, ls1 = 0.f;
#pragma unroll
        for (int nf = 0; nf < 16; nf++) {
            sc[nf][0] = __expf(sc[nf][0] - mn0);
            sc[nf][1] = __expf(sc[nf][1] - mn0);
            sc[nf][2] = __expf(sc[nf][2] - mn1);
            sc[nf][3] = __expf(sc[nf][3] - mn1);
            ls0 += sc[nf][0] + sc[nf][1];
            ls1 += sc[nf][2] + sc[nf][3];
        }
        ls0 += __shfl_xor_sync(0xffffffffu, ls0, 1);
        ls0 += __shfl_xor_sync(0xffffffffu, ls0, 2);
        ls1 += __shfl_xor_sync(0xffffffffu, ls1, 1);
        ls1 += __shfl_xor_sync(0xffffffffu, ls1, 2);
        rl0 = rl0 * c0 + ls0;
        rl1 = rl1 * c1 + ls1;
#pragma unroll
        for (int nf = 0; nf < 8; nf++) {
            o[nf][0] *= c0;
            o[nf][1] *= c0;
            o[nf][2] *= c1;
            o[nf][3] *= c1;
        }

#pragma unroll
        for (int kc = 0; kc < 8; kc++) {
            float v00 = sc[2 * kc][0],     v01 = sc[2 * kc][1];
            float v10 = sc[2 * kc][2],     v11 = sc[2 * kc][3];
            float v20 = sc[2 * kc + 1][0], v21 = sc[2 * kc + 1][1];
            float v30 = sc[2 * kc + 1][2], v31 = sc[2 * kc + 1][3];
            float h00 = __bfloat162float(__float2bfloat16(v00));
            float h01 = __bfloat162float(__float2bfloat16(v01));
            float h10 = __bfloat162float(__float2bfloat16(v10));
            float h11 = __bfloat162float(__float2bfloat16(v11));
            float h20 = __bfloat162float(__float2bfloat16(v20));
            float h21 = __bfloat162float(__float2bfloat16(v21));
            float h30 = __bfloat162float(__float2bfloat16(v30));
            float h31 = __bfloat162float(__float2bfloat16(v31));
            unsigned int pa_h[4];
            unsigned int pa_l[4];
            pa_h[0] = bpack(h00, h01);
            pa_h[1] = bpack(h10, h11);
            pa_h[2] = bpack(h20, h21);
            pa_h[3] = bpack(h30, h31);
            pa_l[0] = bpack(v00 - h00, v01 - h01);
            pa_l[1] = bpack(v10 - h10, v11 - h11);
            pa_l[2] = bpack(v20 - h20, v21 - h21);
            pa_l[3] = bpack(v30 - h30, v31 - h31);

            const unsigned int soff = (unsigned int)(kc * 16 * AP * 2);
            unsigned int vbh[4][4];
            unsigned int vbl[4][4];
#pragma unroll
            for (int dg = 0; dg < 4; dg++) {
                ldsm4t(vbh[dg], sb + 2 * AT_BYTES + kfoff + soff + (unsigned int)(dg * 32));
                ldsm4t(vbl[dg], sb + 3 * AT_BYTES + kfoff + soff + (unsigned int)(dg * 32));
            }
#pragma unroll
            for (int dg = 0; dg < 4; dg++) {
                mma16816(o[2 * dg],     pa_h, vbh[dg][0], vbh[dg][1]);
                mma16816(o[2 * dg + 1], pa_h, vbh[dg][2], vbh[dg][3]);
            }
#pragma unroll
            for (int dg = 0; dg < 4; dg++) {
                mma16816(o[2 * dg],     pa_h, vbl[dg][0], vbl[dg][1]);
                mma16816(o[2 * dg + 1], pa_h, vbl[dg][2], vbl[dg][3]);
            }
#pragma unroll
            for (int dg = 0; dg < 4; dg++) {
                mma16816(o[2 * dg],     pa_l, vbh[dg][0], vbh[dg][1]);
                mma16816(o[2 * dg + 1], pa_l, vbh[dg][2], vbh[dg][3]);
            }
        }
        __syncthreads();

        if (it + 2 < 16)
            attn_issue_tile(SBM, it & 1, it + 2, b, h, t);
    }

    float inv0 = 1.f / rl0;
    float inv1 = 1.f / rl1;
    const int row0 = q0 + w * 16 + gr;
    const int row1 = row0 + 8;
#pragma unroll
    for (int nf = 0; nf < 8; nf++) {
        int d = nf * 8 + 2 * gc;
        float a0 = o[nf][0] * inv0;
        float a1 = o[nf][1] * inv0;
        float b0v = o[nf][2] * inv1;
        float b1v = o[nf][3] * inv1;
        size_t off0 = (size_t)(b * T_SEQ + row0) * D_MODEL + h * 64 + d;
        size_t off1 = (size_t)(b * T_SEQ + row1) * D_MODEL + h * 64 + d;
        float ha0 = __bfloat162float(__float2bfloat16(a0));
        float ha1 = __bfloat162float(__float2bfloat16(a1));
        float hb0 = __bfloat162float(__float2bfloat16(b0v));
        float hb1 = __bfloat162float(__float2bfloat16(b1v));
        *(__nv_bfloat162*)&g_ah[off0] = __floats2bfloat162_rn(ha0, ha1);
        *(__nv_bfloat162*)&g_al[off0] = __floats2bfloat162_rn(a0 - ha0, a1 - ha1);
        *(__nv_bfloat162*)&g_ah[off1] = __floats2bfloat162_rn(hb0, hb1);
        *(__nv_bfloat162*)&g_al[off1] = __floats2bfloat162_rn(b0v - hb0, b1v - hb1);
    }
}

// ---------------------------------------------------------------------------
extern "C" void kernel_launch(void* const* d_in, const int* in_sizes, int n_in,
                              void* d_out, int out_size)
{
    const float* x      = (const float*)d_in[0];
    const float* qkv_w  = (const float*)d_in[1];
    const float* qkv_b  = (const float*)d_in[2];
    const float* out_w  = (const float*)d_in[3];
    const float* out_b  = (const float*)d_in[4];
    float* out = (float*)d_out;

    bf16* xh;  bf16* xl;
    bf16* wqh; bf16* wql;
    bf16* woh; bf16* wol;
    bf16* qh;  bf16* ql;
    bf16* ah;  bf16* al;
    cudaGetSymbolAddress((void**)&xh,  g_xh);
    cudaGetSymbolAddress((void**)&xl,  g_xl);
    cudaGetSymbolAddress((void**)&wqh, g_wqh);
    cudaGetSymbolAddress((void**)&wql, g_wql);
    cudaGetSymbolAddress((void**)&woh, g_woh);
    cudaGetSymbolAddress((void**)&wol, g_wol);
    cudaGetSymbolAddress((void**)&qh,  g_qh);
    cudaGetSymbolAddress((void**)&ql,  g_ql);
    cudaGetSymbolAddress((void**)&ah,  g_ah);
    cudaGetSymbolAddress((void**)&al,  g_al);

    cudaFuncSetAttribute(gemm_fused<1>,
                         cudaFuncAttributeMaxDynamicSharedMemorySize, GSMEM);
    cudaFuncSetAttribute(gemm_fused<0>,
                         cudaFuncAttributeMaxDynamicSharedMemorySize, GSMEM);
    cudaFuncSetAttribute(attn_tc_kernel,
                         cudaFuncAttributeMaxDynamicSharedMemorySize, ASMEM);

    split_all_kernel<<<(SPLIT_N4_ALL + 255) / 256, 256>>>(
        x, qkv_w, out_w, xh, xl, wqh, wql, woh, wol);

    {
        dim3 grid(3 * D_MODEL / 128, MTOT / 128);
        gemm_fused<1><<<grid, 256, GSMEM>>>(xh, xl, wqh, wql, qkv_b,
                                            (float*)0, qh, ql, 3 * D_MODEL);
    }
    {
        dim3 grid(T_SEQ / 128, N_HEAD, BATCH);
        attn_tc_kernel<<<grid, 256, ASMEM>>>();
    }
    {
        dim3 grid(D_MODEL / 128, MTOT / 128);
        gemm_fused<0><<<grid, 256, GSMEM>>>(ah, al, woh, wol, out_b,
                                            out, (bf16*)0, (bf16*)0, D_MODEL);
    }
}